// round 10
// baseline (speedup 1.0000x reference)
#include <cuda_runtime.h>

typedef unsigned long long u64;

__device__ __forceinline__ u64 pk2(float lo, float hi) {
    u64 r;
    asm("mov.b64 %0, {%1, %2};" : "=l"(r)
        : "r"(__float_as_uint(lo)), "r"(__float_as_uint(hi)));
    return r;
}
__device__ __forceinline__ u64 ffma2(u64 a, u64 b, u64 c) {
    u64 d;
    asm("fma.rn.f32x2 %0, %1, %2, %3;" : "=l"(d) : "l"(a), "l"(b), "l"(c));
    return d;
}
__device__ __forceinline__ float f2lo(u64 v) { return __uint_as_float((unsigned)v); }
__device__ __forceinline__ float f2hi(u64 v) { return __uint_as_float((unsigned)(v >> 32)); }

#define MAX_B 16384
// h1 scratch: [sample][pos(l*25+d*5+h)][w] channel-paired (c0,c1) float2
__device__ float2 g_h1[(size_t)MAX_B * 625];

// weights in constant memory (uniform loads -> constant port, off L1TEX)
__constant__ float c_w1[162];   // [oc(2)][81]
__constant__ float c_b1[2];
__constant__ float c_w2[648];   // [oc(4)][ic(2)][81]
__constant__ float c_b2[4];

// ================= kernel 1: layer 1 =================
// 5 samples / 128-thr block; thread=(l,d) computes all 5x5 (h,w) outputs,
// channels (oc0,oc1) packed in f32x2. 125/128 lanes active.
__global__ __launch_bounds__(128, 4)
void l1_kernel(const float* __restrict__ x, int nsamp)
{
    __shared__ float xs[5][2401];

    const int t  = threadIdx.x;
    const int s0 = blockIdx.x * 5;

    {
        int nsm = nsamp - s0; if (nsm > 5) nsm = 5;
        int lim = nsm * 2401;
        const float* xb = x + (size_t)s0 * 2401;
        for (int i = t; i < lim; i += 128) ((float*)xs)[i] = xb[i];
    }
    __syncthreads();

    const int s   = t / 25;
    const int tid = t - s * 25;
    if (t < 125 && s0 + s < nsamp) {
        const int l = tid / 5, d = tid - (tid / 5) * 5;

        const u64 bb = pk2(c_b1[0], c_b1[1]);
        u64 acc[5][5];
        #pragma unroll
        for (int h = 0; h < 5; h++)
            #pragma unroll
            for (int p = 0; p < 5; p++) acc[h][p] = bb;

        #pragma unroll
        for (int i = 0; i < 3; i++)
        #pragma unroll
        for (int j = 0; j < 3; j++) {
            const int pl = i * 3 + j;
            u64 wr[9];
            #pragma unroll
            for (int q = 0; q < 9; q++)
                wr[q] = pk2(c_w1[pl * 9 + q], c_w1[81 + pl * 9 + q]);

            const float* pb = &xs[s][0] + (l + i) * 343 + (d + j) * 49;
            #pragma unroll
            for (int r = 0; r < 7; r++) {
                const float* rp = pb + r * 7;
                u64 xx[7];
                #pragma unroll
                for (int q = 0; q < 7; q++) { float v = rp[q]; xx[q] = pk2(v, v); }
                #pragma unroll
                for (int k = 0; k < 3; k++) {
                    const int h = r - k;
                    if (h >= 0 && h <= 4) {
                        #pragma unroll
                        for (int m = 0; m < 3; m++) {
                            const u64 w = wr[k * 3 + m];
                            #pragma unroll
                            for (int p = 0; p < 5; p++)
                                acc[h][p] = ffma2(xx[p + m], w, acc[h][p]);
                        }
                    }
                }
            }
        }

        float2* hb = &g_h1[(size_t)(s0 + s) * 625 + (size_t)(l * 25 + d * 5) * 5];
        #pragma unroll
        for (int h = 0; h < 5; h++)
            #pragma unroll
            for (int p = 0; p < 5; p++)
                hb[h * 5 + p] = make_float2(fmaxf(f2lo(acc[h][p]), 0.f),
                                            fmaxf(f2hi(acc[h][p]), 0.f));
    }
}

// ================= kernel 2: layer 2 =================
// 9 samples / 256-thr block; thread=(pos in 3^3) computes all 4 oc x 3 w.
// f32x2 lanes = (ic0,ic1) partials; weights from constant memory.
__global__ __launch_bounds__(256)
void l2_kernel(float* __restrict__ out, int nsamp)
{
    __shared__ float2 h1s[9][625];

    const int t  = threadIdx.x;
    const int s0 = blockIdx.x * 9;

    {
        int nsm = nsamp - s0; if (nsm > 9) nsm = 9;
        int tot = nsm * 625;
        const float2* hg = &g_h1[(size_t)s0 * 625];
        for (int i = t; i < tot; i += 256) ((float2*)h1s)[i] = hg[i];
    }
    __syncthreads();

    const int s   = t / 27;
    const int tid = t - s * 27;
    if (t < 243 && s0 + s < nsamp) {
        const int l = tid / 9, d = (tid / 3) % 3, h = tid % 3;

        u64 acc[4][3];
        #pragma unroll
        for (int oc = 0; oc < 4; oc++) {
            u64 ini = pk2(c_b2[oc], 0.f);
            #pragma unroll
            for (int p = 0; p < 3; p++) acc[oc][p] = ini;
        }

        #pragma unroll
        for (int i = 0; i < 3; i++)
        #pragma unroll
        for (int j = 0; j < 3; j++) {
            const int pl = i * 3 + j;
            const float2* vb = &h1s[s][((l + i) * 25 + (d + j) * 5 + h) * 5];

            u64 hh[3][5];
            #pragma unroll
            for (int k = 0; k < 3; k++) {
                const double* rp = (const double*)(vb + k * 5);
                #pragma unroll
                for (int q = 0; q < 5; q++)
                    hh[k][q] = (u64)__double_as_longlong(rp[q]);
            }

            #pragma unroll
            for (int oc = 0; oc < 4; oc++) {
                u64 wr[9];
                #pragma unroll
                for (int q = 0; q < 9; q++)
                    wr[q] = pk2(c_w2[oc * 162 + pl * 9 + q],
                                c_w2[oc * 162 + 81 + pl * 9 + q]);
                #pragma unroll
                for (int k = 0; k < 3; k++)
                #pragma unroll
                for (int m = 0; m < 3; m++) {
                    const u64 w = wr[k * 3 + m];
                    #pragma unroll
                    for (int p = 0; p < 3; p++)
                        acc[oc][p] = ffma2(hh[k][p + m], w, acc[oc][p]);
                }
            }
        }

        float* ob = out + (size_t)(s0 + s) * 324;
        const int pb = ((l * 3 + d) * 3 + h) * 3;
        #pragma unroll
        for (int oc = 0; oc < 4; oc++)
            #pragma unroll
            for (int p = 0; p < 3; p++)
                ob[oc * 81 + pb + p] =
                    fmaxf(f2lo(acc[oc][p]) + f2hi(acc[oc][p]), 0.f);
    }
}

extern "C" void kernel_launch(void* const* d_in, const int* in_sizes, int n_in,
                              void* d_out, int out_size) {
    const float* x = (const float*)d_in[0];
    float* out = (float*)d_out;

    // Stage weights into constant memory (D2D async copies; graph-capturable)
    cudaMemcpyToSymbolAsync(c_w1, d_in[1], 162 * sizeof(float), 0,
                            cudaMemcpyDeviceToDevice);
    cudaMemcpyToSymbolAsync(c_b1, d_in[2], 2 * sizeof(float), 0,
                            cudaMemcpyDeviceToDevice);
    cudaMemcpyToSymbolAsync(c_w2, d_in[3], 648 * sizeof(float), 0,
                            cudaMemcpyDeviceToDevice);
    cudaMemcpyToSymbolAsync(c_b2, d_in[4], 4 * sizeof(float), 0,
                            cudaMemcpyDeviceToDevice);

    int n = in_sizes[0] / 2401;              // B
    if (n > MAX_B) n = MAX_B;
    l1_kernel<<<(n + 4) / 5, 128>>>(x, n);
    l2_kernel<<<(n + 8) / 9, 256>>>(out, n);
}

// round 11
// speedup vs baseline: 1.6123x; 1.6123x over previous
#include <cuda_runtime.h>

typedef unsigned long long u64;

__device__ __forceinline__ u64 pk2(float lo, float hi) {
    u64 r;
    asm("mov.b64 %0, {%1, %2};" : "=l"(r)
        : "r"(__float_as_uint(lo)), "r"(__float_as_uint(hi)));
    return r;
}
__device__ __forceinline__ u64 ffma2(u64 a, u64 b, u64 c) {
    u64 d;
    asm("fma.rn.f32x2 %0, %1, %2, %3;" : "=l"(d) : "l"(a), "l"(b), "l"(c));
    return d;
}
__device__ __forceinline__ float f2lo(u64 v) { return __uint_as_float((unsigned)v); }
__device__ __forceinline__ float f2hi(u64 v) { return __uint_as_float((unsigned)(v >> 32)); }
__device__ __forceinline__ u64 d2u(double d) { return (u64)__double_as_longlong(d); }

#define MAX_B 16384
// h1 scratch, TRANSPOSED: [sample][hw = h*5+w][ld = l*5+d], channel-paired float2.
// l1 lanes (=ld) store contiguously; l2 reads strided (smem, bank-friendly).
__device__ float2 g_h1[(size_t)MAX_B * 625];

// ================= kernel 1: layer 1 =================
// 5 samples / 128-thr block; thread=(l,d) computes all 5x5 (h,w) outputs,
// channels (oc0,oc1) packed in f32x2. 125/128 lanes active.
__global__ __launch_bounds__(128)
void l1_kernel(const float* __restrict__ x,
               const float* __restrict__ w1, const float* __restrict__ b1,
               int nsamp)
{
    __shared__ float xs[5][2401];
    __shared__ __align__(16) float2 w1p[9][10];   // [plane][tap pad] (oc0,oc1)
    __shared__ float2 b1p;

    const int t  = threadIdx.x;
    const int s0 = blockIdx.x * 5;

    for (int i = t; i < 81; i += 128) {
        int pl = i / 9, tp = i - pl * 9;
        w1p[pl][tp] = make_float2(w1[i], w1[81 + i]);
    }
    if (t == 0) b1p = make_float2(b1[0], b1[1]);

    {
        int nsm = nsamp - s0; if (nsm > 5) nsm = 5;
        int lim = nsm * 2401;
        const float* xb = x + (size_t)s0 * 2401;
        for (int i = t; i < lim; i += 128) ((float*)xs)[i] = xb[i];
    }
    __syncthreads();

    const int s   = t / 25;
    const int tid = t - s * 25;
    if (t < 125 && s0 + s < nsamp) {
        const int l = tid / 5, d = tid - (tid / 5) * 5;

        const u64 bb = d2u(*(const double*)&b1p);
        u64 acc[5][5];
        #pragma unroll
        for (int h = 0; h < 5; h++)
            #pragma unroll
            for (int p = 0; p < 5; p++) acc[h][p] = bb;

        #pragma unroll
        for (int i = 0; i < 3; i++)
        #pragma unroll
        for (int j = 0; j < 3; j++) {
            const int pl = i * 3 + j;
            u64 wr[9];
            {
                const double2* wv = (const double2*)&w1p[pl][0];
                double2 a0 = wv[0], a1 = wv[1], a2 = wv[2], a3 = wv[3];
                wr[0] = d2u(a0.x); wr[1] = d2u(a0.y);
                wr[2] = d2u(a1.x); wr[3] = d2u(a1.y);
                wr[4] = d2u(a2.x); wr[5] = d2u(a2.y);
                wr[6] = d2u(a3.x); wr[7] = d2u(a3.y);
                wr[8] = d2u(*(const double*)&w1p[pl][8]);
            }
            const float* pb = &xs[s][0] + (l + i) * 343 + (d + j) * 49;
            #pragma unroll
            for (int r = 0; r < 7; r++) {
                const float* rp = pb + r * 7;
                u64 xx[7];
                #pragma unroll
                for (int q = 0; q < 7; q++) { float v = rp[q]; xx[q] = pk2(v, v); }
                #pragma unroll
                for (int k = 0; k < 3; k++) {
                    const int h = r - k;
                    if (h >= 0 && h <= 4) {
                        #pragma unroll
                        for (int m = 0; m < 3; m++) {
                            const u64 w = wr[k * 3 + m];
                            #pragma unroll
                            for (int p = 0; p < 5; p++)
                                acc[h][p] = ffma2(xx[p + m], w, acc[h][p]);
                        }
                    }
                }
            }
        }

        // coalesced store: lanes (=ld) contiguous per (h,w)
        float2* hb = &g_h1[(size_t)(s0 + s) * 625 + (size_t)(l * 5 + d)];
        #pragma unroll
        for (int h = 0; h < 5; h++)
            #pragma unroll
            for (int p = 0; p < 5; p++)
                hb[(h * 5 + p) * 25] = make_float2(fmaxf(f2lo(acc[h][p]), 0.f),
                                                   fmaxf(f2hi(acc[h][p]), 0.f));
    }
}

// ================= kernel 2: layer 2 =================
// 9 samples / 256-thr block; thread=(pos in 3^3) computes all 4 oc x 3 w.
// f32x2 lanes = (ic0,ic1) partials; weights via smem broadcast.
// h1 layout: [hw][ld] per sample.
__global__ __launch_bounds__(256)
void l2_kernel(const float* __restrict__ w2, const float* __restrict__ b2,
               float* __restrict__ out, int nsamp)
{
    __shared__ float2 h1s[9][625];                 // [s][hw*25 + ld]
    __shared__ __align__(16) float2 w2p[4][9][10]; // [oc][plane][tap pad] (ic0,ic1)
    __shared__ float b2s[4];

    const int t  = threadIdx.x;
    const int s0 = blockIdx.x * 9;

    for (int i = t; i < 324; i += 256) {
        int oc = i / 81, rr = i - oc * 81;
        int pl = rr / 9, tp = rr - pl * 9;
        w2p[oc][pl][tp] = make_float2(w2[oc * 162 + rr], w2[oc * 162 + 81 + rr]);
    }
    if (t < 4) b2s[t] = b2[t];

    {
        int nsm = nsamp - s0; if (nsm > 9) nsm = 9;
        int tot = nsm * 625;
        const float2* hg = &g_h1[(size_t)s0 * 625];
        for (int i = t; i < tot; i += 256) ((float2*)h1s)[i] = hg[i];
    }
    __syncthreads();

    const int s   = t / 27;
    const int tid = t - s * 27;
    if (t < 243 && s0 + s < nsamp) {
        const int l = tid / 9, d = (tid / 3) % 3, h = tid % 3;

        u64 acc[4][3];
        #pragma unroll
        for (int oc = 0; oc < 4; oc++) {
            u64 ini = pk2(b2s[oc], 0.f);
            #pragma unroll
            for (int p = 0; p < 3; p++) acc[oc][p] = ini;
        }

        #pragma unroll
        for (int i = 0; i < 3; i++)
        #pragma unroll
        for (int j = 0; j < 3; j++) {
            const int pl = i * 3 + j;
            const int ldp = (l + i) * 5 + (d + j);   // ld' for this plane
            const float2* vb = &h1s[s][ldp];

            // hh[k][q] = h1[(h+k)*5+q][ld']  (stride 25 float2)
            u64 hh[3][5];
            #pragma unroll
            for (int k = 0; k < 3; k++) {
                const int hwb = (h + k) * 5;
                #pragma unroll
                for (int q = 0; q < 5; q++)
                    hh[k][q] = d2u(*(const double*)(vb + (hwb + q) * 25));
            }

            #pragma unroll
            for (int oc = 0; oc < 4; oc++) {
                u64 wr[9];
                {
                    const double2* wv = (const double2*)&w2p[oc][pl][0];
                    double2 a0 = wv[0], a1 = wv[1], a2 = wv[2], a3 = wv[3];
                    wr[0] = d2u(a0.x); wr[1] = d2u(a0.y);
                    wr[2] = d2u(a1.x); wr[3] = d2u(a1.y);
                    wr[4] = d2u(a2.x); wr[5] = d2u(a2.y);
                    wr[6] = d2u(a3.x); wr[7] = d2u(a3.y);
                    wr[8] = d2u(*(const double*)&w2p[oc][pl][8]);
                }
                #pragma unroll
                for (int k = 0; k < 3; k++)
                #pragma unroll
                for (int m = 0; m < 3; m++) {
                    const u64 w = wr[k * 3 + m];
                    #pragma unroll
                    for (int p = 0; p < 3; p++)
                        acc[oc][p] = ffma2(hh[k][p + m], w, acc[oc][p]);
                }
            }
        }

        float* ob = out + (size_t)(s0 + s) * 324;
        const int pb = ((l * 3 + d) * 3 + h) * 3;
        #pragma unroll
        for (int oc = 0; oc < 4; oc++)
            #pragma unroll
            for (int p = 0; p < 3; p++)
                ob[oc * 81 + pb + p] =
                    fmaxf(f2lo(acc[oc][p]) + f2hi(acc[oc][p]), 0.f);
    }
}

extern "C" void kernel_launch(void* const* d_in, const int* in_sizes, int n_in,
                              void* d_out, int out_size) {
    const float* x  = (const float*)d_in[0];
    const float* w1 = (const float*)d_in[1];
    const float* b1 = (const float*)d_in[2];
    const float* w2 = (const float*)d_in[3];
    const float* b2 = (const float*)d_in[4];
    float* out = (float*)d_out;

    int n = in_sizes[0] / 2401;              // B
    if (n > MAX_B) n = MAX_B;
    l1_kernel<<<(n + 4) / 5, 128>>>(x, w1, b1, n);
    l2_kernel<<<(n + 8) / 9, 256>>>(w2, b2, out, n);
}